// round 8
// baseline (speedup 1.0000x reference)
#include <cuda_runtime.h>

// X-gate on qubit 6 of 13 (op = I_64 ⊗ X ⊗ I_64) applied to two (2048, 8192)
// fp32 tensors. op is a permutation: out[:, j] = in[:, j ^ 64]; in float4
// index space out4[i] = in4[i ^ 16]. Pure streaming permuted copy.
//
// R6: persistent single-wave grid (148 SMs x 8 CTAs) with grid-stride loop
// to eliminate wave-transition overhead and tail imbalance. Per iteration:
// 8 front-batched LDG.128.cs (MLP=8, best config from R3) + 8 STG.128.cs.

static constexpr int BATCH   = 2048;
static constexpr int DIM     = 8192;
static constexpr int N4_PER  = BATCH * (DIM / 4);      // 4,194,304 float4 per tensor
static constexpr int N4_TOT  = 2 * N4_PER;             // 8,388,608
static constexpr int THREADS = 256;
static constexpr int ELEMS   = 8;                      // float4 per thread-iter
static constexpr int CHUNK   = N4_TOT / ELEMS;         // 1,048,576 (= N4_PER/4)
static constexpr int SMS     = 148;
static constexpr int BLOCKS  = SMS * 8;                // 1184 — exactly one wave

__global__ __launch_bounds__(THREADS) void xgate_permute_kernel(
    const float4* __restrict__ x0,
    const float4* __restrict__ x1,
    float4* __restrict__ out)
{
    const int stride = BLOCKS * THREADS;               // 303,104
    for (int t = blockIdx.x * THREADS + threadIdx.x; t < CHUNK; t += stride) {
        const int p = t ^ 16;  // XOR bit 4: swap 64-float column groups

        // Chunks 0..3 read x0, chunks 4..7 read x1 (CHUNK = N4_PER/4).
        float4 v0 = __ldcs(&x0[p + 0 * CHUNK]);
        float4 v1 = __ldcs(&x0[p + 1 * CHUNK]);
        float4 v2 = __ldcs(&x0[p + 2 * CHUNK]);
        float4 v3 = __ldcs(&x0[p + 3 * CHUNK]);
        float4 v4 = __ldcs(&x1[p + 0 * CHUNK]);
        float4 v5 = __ldcs(&x1[p + 1 * CHUNK]);
        float4 v6 = __ldcs(&x1[p + 2 * CHUNK]);
        float4 v7 = __ldcs(&x1[p + 3 * CHUNK]);

        __stcs(&out[t + 0 * CHUNK], v0);
        __stcs(&out[t + 1 * CHUNK], v1);
        __stcs(&out[t + 2 * CHUNK], v2);
        __stcs(&out[t + 3 * CHUNK], v3);
        __stcs(&out[t + 4 * CHUNK], v4);
        __stcs(&out[t + 5 * CHUNK], v5);
        __stcs(&out[t + 6 * CHUNK], v6);
        __stcs(&out[t + 7 * CHUNK], v7);
    }
}

extern "C" void kernel_launch(void* const* d_in, const int* in_sizes, int n_in,
                              void* d_out, int out_size)
{
    const float4* x0 = (const float4*)d_in[0];
    const float4* x1 = (const float4*)d_in[1];
    // d_in[2] is op — ignored (fixed permutation).
    float4* out = (float4*)d_out;

    xgate_permute_kernel<<<BLOCKS, THREADS>>>(x0, x1, out);
}

// round 9
// speedup vs baseline: 1.0463x; 1.0463x over previous
#include <cuda_runtime.h>

// X-gate on qubit 6 of 13 (op = I_64 ⊗ X ⊗ I_64) applied to two (2048, 8192)
// fp32 tensors. op is a permutation: out[:, j] = in[:, j ^ 64]; in 256-bit
// (float8) index space: out8[i] = in8[i ^ 8]. Pure streaming permuted copy.
//
// R7: Blackwell 256-bit global accesses (ld/st.global.cs.v8.f32) — halves
// instruction count and L1tex wavefronts per byte vs float4. 4 front-batched
// v8 loads per thread (128B in flight, same as best ELEMS=8 float4 config),
// exact-fit grid, 32-bit indexing, streaming cache policy.

static constexpr int BATCH   = 2048;
static constexpr int DIM     = 8192;
static constexpr int N8_PER  = BATCH * (DIM / 8);      // 2,097,152 float8 per tensor
static constexpr int N8_TOT  = 2 * N8_PER;             // 4,194,304
static constexpr int THREADS = 256;
static constexpr int ELEMS   = 4;                      // float8 per thread
static constexpr int CHUNK   = N8_TOT / ELEMS;         // 1,048,576 (= N8_PER/2)
static constexpr int BLOCKS  = CHUNK / THREADS;        // 4096

__device__ __forceinline__ void ldg256_cs(const float* p, float* v)
{
    asm volatile(
        "ld.global.cs.v8.f32 {%0,%1,%2,%3,%4,%5,%6,%7}, [%8];"
        : "=f"(v[0]), "=f"(v[1]), "=f"(v[2]), "=f"(v[3]),
          "=f"(v[4]), "=f"(v[5]), "=f"(v[6]), "=f"(v[7])
        : "l"(p));
}

__device__ __forceinline__ void stg256_cs(float* p, const float* v)
{
    asm volatile(
        "st.global.cs.v8.f32 [%0], {%1,%2,%3,%4,%5,%6,%7,%8};"
        :: "l"(p),
           "f"(v[0]), "f"(v[1]), "f"(v[2]), "f"(v[3]),
           "f"(v[4]), "f"(v[5]), "f"(v[6]), "f"(v[7])
        : "memory");
}

__global__ __launch_bounds__(THREADS) void xgate_permute_kernel(
    const float* __restrict__ x0,
    const float* __restrict__ x1,
    float* __restrict__ out)
{
    const int t = blockIdx.x * THREADS + threadIdx.x;
    const int p = t ^ 8;   // XOR bit 3 of float8 index (swap 64-float groups)

    // Chunks 0,1 read x0; chunks 2,3 read x1 (CHUNK = N8_PER/2).
    // Front-batch all 4 v8 loads for MLP.
    float v0[8], v1[8], v2[8], v3[8];
    ldg256_cs(x0 + (size_t)(p + 0 * CHUNK) * 8, v0);
    ldg256_cs(x0 + (size_t)(p + 1 * CHUNK) * 8, v1);
    ldg256_cs(x1 + (size_t)(p + 0 * CHUNK) * 8, v2);
    ldg256_cs(x1 + (size_t)(p + 1 * CHUNK) * 8, v3);

    stg256_cs(out + (size_t)(t + 0 * CHUNK) * 8, v0);
    stg256_cs(out + (size_t)(t + 1 * CHUNK) * 8, v1);
    stg256_cs(out + (size_t)(t + 2 * CHUNK) * 8, v2);
    stg256_cs(out + (size_t)(t + 3 * CHUNK) * 8, v3);
}

extern "C" void kernel_launch(void* const* d_in, const int* in_sizes, int n_in,
                              void* d_out, int out_size)
{
    const float* x0 = (const float*)d_in[0];
    const float* x1 = (const float*)d_in[1];
    // d_in[2] is op — ignored (fixed permutation).
    float* out = (float*)d_out;

    xgate_permute_kernel<<<BLOCKS, THREADS>>>(x0, x1, out);
}